// round 2
// baseline (speedup 1.0000x reference)
#include <cuda_runtime.h>
#include <math.h>

#define MAXN 50000
#define MAXE 800000
#define MAXEP (MAXN + MAXE)

// ---------------- scratch (device globals; no allocation allowed) ----------------
__device__ float g_xl1[MAXN * 128];
__device__ float g_xr1[MAXN * 128];
__device__ float g_res[MAXN * 32];
__device__ float g_a1[(size_t)MAXEP * 4];
__device__ float g_denom1[MAXN * 4];
__device__ float g_agg1[MAXN * 128];
__device__ float g_h1[MAXN * 128];
__device__ float g_xl2[MAXN * 32];
__device__ float g_xr2[MAXN * 32];
__device__ float g_a2[MAXEP];
__device__ float g_denom2[MAXN];
__device__ float g_agg2[MAXN * 32];
__device__ double g_sum1[128], g_sq1[128];
__device__ double g_sum2[32], g_sq2[32];
__device__ float g_scale1[128], g_shift1[128];
__device__ float g_scale2[32], g_shift2[32];

// vector reduction (no-return atomic add), sm_90+
__device__ __forceinline__ void red_add_f4(float* addr, float4 v) {
    asm volatile("red.global.add.v4.f32 [%0], {%1,%2,%3,%4};"
                 :: "l"(addr), "f"(v.x), "f"(v.y), "f"(v.z), "f"(v.w)
                 : "memory");
}

// ---------------- fused dense transform: out = X @ W^T (+bias), K=128 ----------------
// Features are the concatenation of up to 3 weight matrices (row-major [F?][128]).
// Block: 64 rows x 64 features, 256 threads, 4x4 register tile per thread.
// K is split into 2 chunks of 64 to fit the 48KB static-smem limit.
__global__ void transform_kernel(
    const float* __restrict__ X, int n,
    const float* __restrict__ W0, const float* __restrict__ W1, const float* __restrict__ W2,
    int F0, int F1, int F2,
    const float* __restrict__ b0, const float* __restrict__ b1, const float* __restrict__ b2,
    float* __restrict__ o0, float* __restrict__ o1, float* __restrict__ o2,
    int ld0, int ld1, int ld2)
{
    __shared__ float Xs[64][68];
    __shared__ float Ws[64][68];
    const int rb = blockIdx.x * 64;
    const int fb = blockIdx.y * 64;
    const int tid = threadIdx.x;
    const int Ft = F0 + F1 + F2;

    const int tx = tid & 15, ty = tid >> 4;
    float acc[4][4];
    #pragma unroll
    for (int i = 0; i < 4; i++)
        #pragma unroll
        for (int j = 0; j < 4; j++) acc[i][j] = 0.f;

    // resolve W row pointer + bias once per thread's load rows
    for (int kk = 0; kk < 128; kk += 64) {
        // load X tile [64][64] (float4 coalesced): 4096 floats = 4 float4/thread
        #pragma unroll
        for (int it = 0; it < 4; it++) {
            int idx = it * 256 + tid;
            int r = idx >> 4;            // 0..63
            int kc = (idx & 15) << 2;    // 0..60
            float4 v = make_float4(0.f, 0.f, 0.f, 0.f);
            int row = rb + r;
            if (row < n) v = *(const float4*)(X + (size_t)row * 128 + kk + kc);
            Xs[r][kc] = v.x; Xs[r][kc + 1] = v.y; Xs[r][kc + 2] = v.z; Xs[r][kc + 3] = v.w;
        }
        // load W tile [64][64]
        #pragma unroll
        for (int it = 0; it < 4; it++) {
            int idx = it * 256 + tid;
            int f = idx >> 4;
            int kc = (idx & 15) << 2;
            int gf = fb + f;
            float4 v = make_float4(0.f, 0.f, 0.f, 0.f);
            const float* Wp = nullptr;
            int lf = gf;
            if (gf < F0) { Wp = W0; }
            else if (gf < F0 + F1) { Wp = W1; lf = gf - F0; }
            else if (gf < Ft) { Wp = W2; lf = gf - F0 - F1; }
            if (Wp) v = *(const float4*)(Wp + (size_t)lf * 128 + kk + kc);
            Ws[f][kc] = v.x; Ws[f][kc + 1] = v.y; Ws[f][kc + 2] = v.z; Ws[f][kc + 3] = v.w;
        }
        __syncthreads();

        #pragma unroll 8
        for (int k = 0; k < 64; k++) {
            float a[4], b[4];
            #pragma unroll
            for (int i = 0; i < 4; i++) a[i] = Xs[ty * 4 + i][k];
            #pragma unroll
            for (int j = 0; j < 4; j++) b[j] = Ws[tx * 4 + j][k];
            #pragma unroll
            for (int i = 0; i < 4; i++)
                #pragma unroll
                for (int j = 0; j < 4; j++) acc[i][j] += a[i] * b[j];
        }
        __syncthreads();
    }

    #pragma unroll
    for (int i = 0; i < 4; i++) {
        int row = rb + ty * 4 + i;
        if (row >= n) break;
        #pragma unroll
        for (int j = 0; j < 4; j++) {
            int gf = fb + tx * 4 + j;
            if (gf < F0) {
                float bb = b0 ? b0[gf] : 0.f;
                o0[(size_t)row * ld0 + gf] = acc[i][j] + bb;
            } else if (gf < F0 + F1) {
                int lf = gf - F0;
                float bb = b1 ? b1[lf] : 0.f;
                o1[(size_t)row * ld1 + lf] = acc[i][j] + bb;
            } else if (gf < Ft) {
                int lf = gf - F0 - F1;
                float bb = b2 ? b2[lf] : 0.f;
                o2[(size_t)row * ld2 + lf] = acc[i][j] + bb;
            }
        }
    }
}

// ---------------- conv1 edge pass A: logits -> exp -> denom ----------------
// warp per edge; lane handles channel `lane` of each of the 4 heads.
__global__ void edge_logits1(const int* __restrict__ ei, int E, int N,
                             const float* __restrict__ att)
{
    int gw = (blockIdx.x * blockDim.x + threadIdx.x) >> 5;
    int lane = threadIdx.x & 31;
    int EP = E + N;
    if (gw >= EP) return;
    int s, d;
    if (gw < E) { s = ei[gw]; d = ei[E + gw]; }
    else { s = gw - E; d = s; }

    const float* xls = g_xl1 + (size_t)s * 128;
    const float* xrd = g_xr1 + (size_t)d * 128;
    float l0, l1, l2, l3;
    {
        int f = lane;
        float m = xls[f] + xrd[f];
        l0 = (m > 0.f ? m : 0.2f * m) * att[f];
        f = 32 + lane;
        m = xls[f] + xrd[f];
        l1 = (m > 0.f ? m : 0.2f * m) * att[f];
        f = 64 + lane;
        m = xls[f] + xrd[f];
        l2 = (m > 0.f ? m : 0.2f * m) * att[f];
        f = 96 + lane;
        m = xls[f] + xrd[f];
        l3 = (m > 0.f ? m : 0.2f * m) * att[f];
    }
    #pragma unroll
    for (int o = 16; o > 0; o >>= 1) {
        l0 += __shfl_xor_sync(0xffffffffu, l0, o);
        l1 += __shfl_xor_sync(0xffffffffu, l1, o);
        l2 += __shfl_xor_sync(0xffffffffu, l2, o);
        l3 += __shfl_xor_sync(0xffffffffu, l3, o);
    }
    if (lane < 4) {
        float lg = (lane == 0) ? l0 : (lane == 1) ? l1 : (lane == 2) ? l2 : l3;
        float a = expf(lg);
        g_a1[(size_t)gw * 4 + lane] = a;
        atomicAdd(&g_denom1[(size_t)d * 4 + lane], a);
    }
}

// ---------------- conv1 edge pass B: weighted scatter-add ----------------
__global__ void edge_agg1(const int* __restrict__ ei, int E, int N)
{
    int gw = (blockIdx.x * blockDim.x + threadIdx.x) >> 5;
    int lane = threadIdx.x & 31;
    int EP = E + N;
    if (gw >= EP) return;
    int s, d;
    if (gw < E) { s = ei[gw]; d = ei[E + gw]; }
    else { s = gw - E; d = s; }

    int h = lane >> 3;  // features 4*lane..4*lane+3 are all head lane/8
    float a = g_a1[(size_t)gw * 4 + h];
    float den = g_denom1[(size_t)d * 4 + h];
    float alpha = a / (den + 1e-16f);

    float4 v = *(const float4*)(g_xl1 + (size_t)s * 128 + lane * 4);
    v.x *= alpha; v.y *= alpha; v.z *= alpha; v.w *= alpha;
    red_add_f4(g_agg1 + (size_t)d * 128 + lane * 4, v);
}

// ---------------- conv2 edge passes ----------------
__global__ void edge_logits2(const int* __restrict__ ei, int E, int N,
                             const float* __restrict__ att)
{
    int gw = (blockIdx.x * blockDim.x + threadIdx.x) >> 5;
    int lane = threadIdx.x & 31;
    int EP = E + N;
    if (gw >= EP) return;
    int s, d;
    if (gw < E) { s = ei[gw]; d = ei[E + gw]; }
    else { s = gw - E; d = s; }

    float m = g_xl2[(size_t)s * 32 + lane] + g_xr2[(size_t)d * 32 + lane];
    float e = m > 0.f ? m : 0.2f * m;
    float l = e * att[lane];
    #pragma unroll
    for (int o = 16; o > 0; o >>= 1) l += __shfl_xor_sync(0xffffffffu, l, o);
    if (lane == 0) {
        float a = expf(l);
        g_a2[gw] = a;
        atomicAdd(&g_denom2[d], a);
    }
}

__global__ void edge_agg2(const int* __restrict__ ei, int E, int N)
{
    int gw = (blockIdx.x * blockDim.x + threadIdx.x) >> 5;
    int lane = threadIdx.x & 31;
    int EP = E + N;
    if (gw >= EP) return;
    int s, d;
    if (gw < E) { s = ei[gw]; d = ei[E + gw]; }
    else { s = gw - E; d = s; }

    float a = g_a2[gw];
    float den = g_denom2[d];
    float alpha = a / (den + 1e-16f);
    if (lane < 8) {
        float4 v = *(const float4*)(g_xl2 + (size_t)s * 32 + lane * 4);
        v.x *= alpha; v.y *= alpha; v.z *= alpha; v.w *= alpha;
        red_add_f4(g_agg2 + (size_t)d * 32 + lane * 4, v);
    }
}

// ---------------- batch-norm statistics ----------------
template <int C>
__global__ void bn_stats(const float* __restrict__ h, const float* __restrict__ bias,
                         int n, double* __restrict__ sum, double* __restrict__ sq)
{
    const int RPB = 256 / C;
    int tid = threadIdx.x;
    int c = tid % C;
    int rsub = tid / C;
    float bc = bias[c];
    float s = 0.f, s2 = 0.f;
    for (int row = blockIdx.x * RPB + rsub; row < n; row += gridDim.x * RPB) {
        float v = h[(size_t)row * C + c] + bc;
        s += v;
        s2 += v * v;
    }
    __shared__ float ss[256], ss2[256];
    ss[tid] = s; ss2[tid] = s2;
    __syncthreads();
    if (tid < C) {
        float t = 0.f, t2 = 0.f;
        #pragma unroll
        for (int r = 0; r < RPB; r++) { t += ss[r * C + c]; t2 += ss2[r * C + c]; }
        atomicAdd(&sum[c], (double)t);
        atomicAdd(&sq[c], (double)t2);
    }
}

__global__ void bn_prep(const double* __restrict__ sum, const double* __restrict__ sq,
                        int n, int C,
                        const float* __restrict__ g, const float* __restrict__ b,
                        const float* __restrict__ bias,
                        float* __restrict__ scale, float* __restrict__ shift)
{
    int c = threadIdx.x;
    if (c >= C) return;
    double mu = sum[c] / n;
    double var = sq[c] / n - mu * mu;
    float istd = rsqrtf((float)var + 1e-5f);
    float sc = istd * g[c];
    scale[c] = sc;
    // value fed to BN is raw+bias:  (raw+bias-mu)*sc + b
    shift[c] = (bias[c] - (float)mu) * sc + b[c];
}

// BN + ELU elementwise (C must be power of two)
__global__ void bn_apply_elu(const float* __restrict__ in, float* __restrict__ out,
                             int total, int Cmask,
                             const float* __restrict__ scale, const float* __restrict__ shift)
{
    int i = blockIdx.x * blockDim.x + threadIdx.x;
    if (i >= total) return;
    int c = i & Cmask;
    float v = in[i] * scale[c] + shift[c];
    out[i] = v > 0.f ? v : expm1f(v);
}

// ---------------- final: BN2 + residual + ELU + [N,32]@[32,2] head ----------------
__global__ void finalize_kernel(const float* __restrict__ linW, const float* __restrict__ linb,
                                float* __restrict__ out, int n)
{
    int gw = (blockIdx.x * blockDim.x + threadIdx.x) >> 5;
    int lane = threadIdx.x & 31;
    if (gw >= n) return;
    float v = g_agg2[(size_t)gw * 32 + lane] * g_scale2[lane] + g_shift2[lane]
            + g_res[(size_t)gw * 32 + lane];
    v = v > 0.f ? v : expm1f(v);
    float o0 = v * linW[lane];
    float o1 = v * linW[32 + lane];
    #pragma unroll
    for (int o = 16; o > 0; o >>= 1) {
        o0 += __shfl_xor_sync(0xffffffffu, o0, o);
        o1 += __shfl_xor_sync(0xffffffffu, o1, o);
    }
    if (lane == 0) {
        out[(size_t)gw * 2] = o0 + linb[0];
        out[(size_t)gw * 2 + 1] = o1 + linb[1];
    }
}

// ---------------- host launcher ----------------
extern "C" void kernel_launch(void* const* d_in, const int* in_sizes, int n_in,
                              void* d_out, int out_size)
{
    const float* x      = (const float*)d_in[0];
    const int*   ei     = (const int*)d_in[1];
    const float* Wl1    = (const float*)d_in[2];
    const float* bl1    = (const float*)d_in[3];
    const float* Wr1    = (const float*)d_in[4];
    const float* br1    = (const float*)d_in[5];
    const float* att1   = (const float*)d_in[6];
    const float* bias1  = (const float*)d_in[7];
    const float* Wl2    = (const float*)d_in[8];
    const float* bl2    = (const float*)d_in[9];
    const float* Wr2    = (const float*)d_in[10];
    const float* br2    = (const float*)d_in[11];
    const float* att2   = (const float*)d_in[12];
    const float* bias2  = (const float*)d_in[13];
    const float* bn1_g  = (const float*)d_in[14];
    const float* bn1_b  = (const float*)d_in[15];
    const float* bn2_g  = (const float*)d_in[16];
    const float* bn2_b  = (const float*)d_in[17];
    const float* skipW  = (const float*)d_in[18];
    const float* linW   = (const float*)d_in[19];
    const float* linb   = (const float*)d_in[20];
    float* out = (float*)d_out;

    const int N = in_sizes[0] / 128;
    const int E = in_sizes[1] / 2;
    const int EP = E + N;

    // zero accumulators (memset nodes are graph-capturable)
    void* p;
    cudaGetSymbolAddress(&p, g_denom1); cudaMemsetAsync(p, 0, (size_t)N * 4 * sizeof(float));
    cudaGetSymbolAddress(&p, g_agg1);   cudaMemsetAsync(p, 0, (size_t)N * 128 * sizeof(float));
    cudaGetSymbolAddress(&p, g_denom2); cudaMemsetAsync(p, 0, (size_t)N * sizeof(float));
    cudaGetSymbolAddress(&p, g_agg2);   cudaMemsetAsync(p, 0, (size_t)N * 32 * sizeof(float));
    cudaGetSymbolAddress(&p, g_sum1);   cudaMemsetAsync(p, 0, 128 * sizeof(double));
    cudaGetSymbolAddress(&p, g_sq1);    cudaMemsetAsync(p, 0, 128 * sizeof(double));
    cudaGetSymbolAddress(&p, g_sum2);   cudaMemsetAsync(p, 0, 32 * sizeof(double));
    cudaGetSymbolAddress(&p, g_sq2);    cudaMemsetAsync(p, 0, 32 * sizeof(double));

    float *d_xl1, *d_xr1, *d_res, *d_h1, *d_xl2, *d_xr2, *d_agg1, *d_agg2;
    float *d_scale1, *d_shift1, *d_scale2, *d_shift2;
    double *d_sum1, *d_sq1, *d_sum2, *d_sq2;
    cudaGetSymbolAddress((void**)&d_xl1, g_xl1);
    cudaGetSymbolAddress((void**)&d_xr1, g_xr1);
    cudaGetSymbolAddress((void**)&d_res, g_res);
    cudaGetSymbolAddress((void**)&d_h1, g_h1);
    cudaGetSymbolAddress((void**)&d_xl2, g_xl2);
    cudaGetSymbolAddress((void**)&d_xr2, g_xr2);
    cudaGetSymbolAddress((void**)&d_agg1, g_agg1);
    cudaGetSymbolAddress((void**)&d_agg2, g_agg2);
    cudaGetSymbolAddress((void**)&d_scale1, g_scale1);
    cudaGetSymbolAddress((void**)&d_shift1, g_shift1);
    cudaGetSymbolAddress((void**)&d_scale2, g_scale2);
    cudaGetSymbolAddress((void**)&d_shift2, g_shift2);
    cudaGetSymbolAddress((void**)&d_sum1, g_sum1);
    cudaGetSymbolAddress((void**)&d_sq1, g_sq1);
    cudaGetSymbolAddress((void**)&d_sum2, g_sum2);
    cudaGetSymbolAddress((void**)&d_sq2, g_sq2);

    const int rowBlocks = (N + 63) / 64;
    const int edgeBlocks = (EP * 32 + 255) / 256;

    // conv1 transforms + residual: 288 features = Wl1(128) | Wr1(128) | skip(32)
    transform_kernel<<<dim3(rowBlocks, 5), 256>>>(
        x, N, Wl1, Wr1, skipW, 128, 128, 32,
        bl1, br1, nullptr,
        d_xl1, d_xr1, d_res, 128, 128, 32);

    edge_logits1<<<edgeBlocks, 256>>>(ei, E, N, att1);
    edge_agg1<<<edgeBlocks, 256>>>(ei, E, N);

    bn_stats<128><<<128, 256>>>(d_agg1, bias1, N, d_sum1, d_sq1);
    bn_prep<<<1, 128>>>(d_sum1, d_sq1, N, 128, bn1_g, bn1_b, bias1, d_scale1, d_shift1);
    {
        int total = N * 128;
        bn_apply_elu<<<(total + 255) / 256, 256>>>(d_agg1, d_h1, total, 127, d_scale1, d_shift1);
    }

    // conv2 transforms: 64 features = Wl2(32) | Wr2(32)
    transform_kernel<<<dim3(rowBlocks, 1), 256>>>(
        d_h1, N, Wl2, Wr2, nullptr, 32, 32, 0,
        bl2, br2, nullptr,
        d_xl2, d_xr2, nullptr, 32, 32, 0);

    edge_logits2<<<edgeBlocks, 256>>>(ei, E, N, att2);
    edge_agg2<<<edgeBlocks, 256>>>(ei, E, N);

    bn_stats<32><<<128, 256>>>(d_agg2, bias2, N, d_sum2, d_sq2);
    bn_prep<<<1, 32>>>(d_sum2, d_sq2, N, 32, bn2_g, bn2_b, bias2, d_scale2, d_shift2);

    finalize_kernel<<<(N * 32 + 255) / 256, 256>>>(linW, linb, out, N);
}

// round 3
// speedup vs baseline: 1.1208x; 1.1208x over previous
#include <cuda_runtime.h>
#include <math.h>

#define MAXN 50000
#define MAXE 800000
#define MAXEP (MAXN + MAXE)

// ---------------- scratch (device globals; no allocation allowed) ----------------
__device__ float g_xl1[MAXN * 128];
__device__ float g_xr1[MAXN * 128];
__device__ float g_res[MAXN * 32];
__device__ float g_a1[(size_t)MAXEP * 4];
__device__ float g_denom1[MAXN * 4];
__device__ float g_agg1[MAXN * 128];
__device__ float g_h1[MAXN * 128];
__device__ float g_xl2[MAXN * 32];
__device__ float g_xr2[MAXN * 32];
__device__ float g_a2[MAXEP];
__device__ float g_denom2[MAXN];
__device__ float g_agg2[MAXN * 32];
__device__ double g_sum1[128], g_sq1[128];
__device__ double g_sum2[32], g_sq2[32];
__device__ float g_scale1[128], g_shift1[128];
__device__ float g_scale2[32], g_shift2[32];

// vector reduction (no-return atomic add), sm_90+
__device__ __forceinline__ void red_add_f4(float* addr, float4 v) {
    asm volatile("red.global.add.v4.f32 [%0], {%1,%2,%3,%4};"
                 :: "l"(addr), "f"(v.x), "f"(v.y), "f"(v.z), "f"(v.w)
                 : "memory");
}

// ---------------- fused dense transform: out = X @ W^T (+bias), K=128 ----------------
__global__ void transform_kernel(
    const float* __restrict__ X, int n,
    const float* __restrict__ W0, const float* __restrict__ W1, const float* __restrict__ W2,
    int F0, int F1, int F2,
    const float* __restrict__ b0, const float* __restrict__ b1, const float* __restrict__ b2,
    float* __restrict__ o0, float* __restrict__ o1, float* __restrict__ o2,
    int ld0, int ld1, int ld2)
{
    __shared__ float Xs[64][68];
    __shared__ float Ws[64][68];
    const int rb = blockIdx.x * 64;
    const int fb = blockIdx.y * 64;
    const int tid = threadIdx.x;
    const int Ft = F0 + F1 + F2;

    const int tx = tid & 15, ty = tid >> 4;
    float acc[4][4];
    #pragma unroll
    for (int i = 0; i < 4; i++)
        #pragma unroll
        for (int j = 0; j < 4; j++) acc[i][j] = 0.f;

    for (int kk = 0; kk < 128; kk += 64) {
        #pragma unroll
        for (int it = 0; it < 4; it++) {
            int idx = it * 256 + tid;
            int r = idx >> 4;
            int kc = (idx & 15) << 2;
            float4 v = make_float4(0.f, 0.f, 0.f, 0.f);
            int row = rb + r;
            if (row < n) v = *(const float4*)(X + (size_t)row * 128 + kk + kc);
            Xs[r][kc] = v.x; Xs[r][kc + 1] = v.y; Xs[r][kc + 2] = v.z; Xs[r][kc + 3] = v.w;
        }
        #pragma unroll
        for (int it = 0; it < 4; it++) {
            int idx = it * 256 + tid;
            int f = idx >> 4;
            int kc = (idx & 15) << 2;
            int gf = fb + f;
            float4 v = make_float4(0.f, 0.f, 0.f, 0.f);
            const float* Wp = nullptr;
            int lf = gf;
            if (gf < F0) { Wp = W0; }
            else if (gf < F0 + F1) { Wp = W1; lf = gf - F0; }
            else if (gf < Ft) { Wp = W2; lf = gf - F0 - F1; }
            if (Wp) v = *(const float4*)(Wp + (size_t)lf * 128 + kk + kc);
            Ws[f][kc] = v.x; Ws[f][kc + 1] = v.y; Ws[f][kc + 2] = v.z; Ws[f][kc + 3] = v.w;
        }
        __syncthreads();

        #pragma unroll 8
        for (int k = 0; k < 64; k++) {
            float a[4], b[4];
            #pragma unroll
            for (int i = 0; i < 4; i++) a[i] = Xs[ty * 4 + i][k];
            #pragma unroll
            for (int j = 0; j < 4; j++) b[j] = Ws[tx * 4 + j][k];
            #pragma unroll
            for (int i = 0; i < 4; i++)
                #pragma unroll
                for (int j = 0; j < 4; j++) acc[i][j] += a[i] * b[j];
        }
        __syncthreads();
    }

    #pragma unroll
    for (int i = 0; i < 4; i++) {
        int row = rb + ty * 4 + i;
        if (row >= n) break;
        #pragma unroll
        for (int j = 0; j < 4; j++) {
            int gf = fb + tx * 4 + j;
            if (gf < F0) {
                float bb = b0 ? b0[gf] : 0.f;
                o0[(size_t)row * ld0 + gf] = acc[i][j] + bb;
            } else if (gf < F0 + F1) {
                int lf = gf - F0;
                float bb = b1 ? b1[lf] : 0.f;
                o1[(size_t)row * ld1 + lf] = acc[i][j] + bb;
            } else if (gf < Ft) {
                int lf = gf - F0 - F1;
                float bb = b2 ? b2[lf] : 0.f;
                o2[(size_t)row * ld2 + lf] = acc[i][j] + bb;
            }
        }
    }
}

// ---------------- conv1 edge pass A: logits -> exp -> denom ----------------
// warp per edge; lane loads float4 of features [4*lane, 4*lane+4).
// head(f) = f>>5, so lane's 4 features share head = lane>>3.
__global__ void edge_logits1(const int* __restrict__ ei, int E, int N,
                             const float* __restrict__ att)
{
    int gw = (blockIdx.x * blockDim.x + threadIdx.x) >> 5;
    int lane = threadIdx.x & 31;
    int EP = E + N;
    if (gw >= EP) return;
    int s, d;
    if (gw < E) { s = ei[gw]; d = ei[E + gw]; }
    else { s = gw - E; d = s; }

    float4 xl = *(const float4*)(g_xl1 + (size_t)s * 128 + lane * 4);
    float4 xr = *(const float4*)(g_xr1 + (size_t)d * 128 + lane * 4);
    float4 at = *(const float4*)(att + lane * 4);
    float m0 = xl.x + xr.x, m1 = xl.y + xr.y, m2 = xl.z + xr.z, m3 = xl.w + xr.w;
    float l = (m0 > 0.f ? m0 : 0.2f * m0) * at.x
            + (m1 > 0.f ? m1 : 0.2f * m1) * at.y
            + (m2 > 0.f ? m2 : 0.2f * m2) * at.z
            + (m3 > 0.f ? m3 : 0.2f * m3) * at.w;
    // reduce within 8-lane groups (same head)
    l += __shfl_xor_sync(0xffffffffu, l, 1);
    l += __shfl_xor_sync(0xffffffffu, l, 2);
    l += __shfl_xor_sync(0xffffffffu, l, 4);
    if ((lane & 7) == 0) {
        int h = lane >> 3;
        float a = expf(l);
        g_a1[(size_t)gw * 4 + h] = a;
        atomicAdd(&g_denom1[(size_t)d * 4 + h], a);
    }
}

// ---------------- conv1 edge pass B: weighted scatter-add ----------------
__global__ void edge_agg1(const int* __restrict__ ei, int E, int N)
{
    int gw = (blockIdx.x * blockDim.x + threadIdx.x) >> 5;
    int lane = threadIdx.x & 31;
    int EP = E + N;
    if (gw >= EP) return;
    int s, d;
    if (gw < E) { s = ei[gw]; d = ei[E + gw]; }
    else { s = gw - E; d = s; }

    int h = lane >> 3;
    float a = g_a1[(size_t)gw * 4 + h];
    float den = g_denom1[(size_t)d * 4 + h];
    float alpha = a / (den + 1e-16f);

    float4 v = *(const float4*)(g_xl1 + (size_t)s * 128 + lane * 4);
    v.x *= alpha; v.y *= alpha; v.z *= alpha; v.w *= alpha;
    red_add_f4(g_agg1 + (size_t)d * 128 + lane * 4, v);
}

// ---------------- conv2 edge passes ----------------
__global__ void edge_logits2(const int* __restrict__ ei, int E, int N,
                             const float* __restrict__ att)
{
    int gw = (blockIdx.x * blockDim.x + threadIdx.x) >> 5;
    int lane = threadIdx.x & 31;
    int EP = E + N;
    if (gw >= EP) return;
    int s, d;
    if (gw < E) { s = ei[gw]; d = ei[E + gw]; }
    else { s = gw - E; d = s; }

    float m = g_xl2[(size_t)s * 32 + lane] + g_xr2[(size_t)d * 32 + lane];
    float e = m > 0.f ? m : 0.2f * m;
    float l = e * att[lane];
    #pragma unroll
    for (int o = 16; o > 0; o >>= 1) l += __shfl_xor_sync(0xffffffffu, l, o);
    if (lane == 0) {
        float a = expf(l);
        g_a2[gw] = a;
        atomicAdd(&g_denom2[d], a);
    }
}

__global__ void edge_agg2(const int* __restrict__ ei, int E, int N)
{
    int gw = (blockIdx.x * blockDim.x + threadIdx.x) >> 5;
    int lane = threadIdx.x & 31;
    int EP = E + N;
    if (gw >= EP) return;
    int s, d;
    if (gw < E) { s = ei[gw]; d = ei[E + gw]; }
    else { s = gw - E; d = s; }

    float a = g_a2[gw];
    float den = g_denom2[d];
    float alpha = a / (den + 1e-16f);
    if (lane < 8) {
        float4 v = *(const float4*)(g_xl2 + (size_t)s * 32 + lane * 4);
        v.x *= alpha; v.y *= alpha; v.z *= alpha; v.w *= alpha;
        red_add_f4(g_agg2 + (size_t)d * 32 + lane * 4, v);
    }
}

// ---------------- batch-norm statistics (float4, grid-stride, high MLP) ----------------
// C/4 must divide 256. Each thread owns a fixed 4-channel group.
template <int C>
__global__ void bn_stats(const float* __restrict__ h, const float* __restrict__ bias,
                         int n, double* __restrict__ sum, double* __restrict__ sq)
{
    const int Q = C / 4;              // float4s per row
    int tid = threadIdx.x;
    int q = tid & (Q - 1);            // which float4 within row
    float4 bc = *(const float4*)(bias + q * 4);
    float s0 = 0.f, s1 = 0.f, s2v = 0.f, s3 = 0.f;
    float t0 = 0.f, t1 = 0.f, t2 = 0.f, t3 = 0.f;
    size_t total4 = (size_t)n * Q;
    const float4* h4 = (const float4*)h;
    for (size_t j = (size_t)blockIdx.x * blockDim.x + tid; j < total4;
         j += (size_t)gridDim.x * blockDim.x) {
        float4 v = h4[j];
        float a0 = v.x + bc.x, a1 = v.y + bc.y, a2 = v.z + bc.z, a3 = v.w + bc.w;
        s0 += a0; t0 += a0 * a0;
        s1 += a1; t1 += a1 * a1;
        s2v += a2; t2 += a2 * a2;
        s3 += a3; t3 += a3 * a3;
    }
    __shared__ float red[8][256];
    red[0][tid] = s0; red[1][tid] = s1; red[2][tid] = s2v; red[3][tid] = s3;
    red[4][tid] = t0; red[5][tid] = t1; red[6][tid] = t2; red[7][tid] = t3;
    __syncthreads();
    if (tid < Q) {
        const int G = 256 / Q;
        #pragma unroll
        for (int k = 0; k < 8; k++) {
            float acc = 0.f;
            for (int r = 0; r < G; r++) acc += red[k][tid + r * Q];
            if (k < 4) atomicAdd(&sum[tid * 4 + k], (double)acc);
            else       atomicAdd(&sq[tid * 4 + (k - 4)], (double)acc);
        }
    }
}

__global__ void bn_prep(const double* __restrict__ sum, const double* __restrict__ sq,
                        int n, int C,
                        const float* __restrict__ g, const float* __restrict__ b,
                        const float* __restrict__ bias,
                        float* __restrict__ scale, float* __restrict__ shift)
{
    int c = threadIdx.x;
    if (c >= C) return;
    double mu = sum[c] / n;
    double var = sq[c] / n - mu * mu;
    float istd = rsqrtf((float)var + 1e-5f);
    float sc = istd * g[c];
    scale[c] = sc;
    shift[c] = (bias[c] - (float)mu) * sc + b[c];
}

// BN + ELU elementwise, float4 (C divisible by 4, power of two)
__global__ void bn_apply_elu4(const float4* __restrict__ in, float4* __restrict__ out,
                              int total4, int Qmask,
                              const float* __restrict__ scale, const float* __restrict__ shift)
{
    int j = blockIdx.x * blockDim.x + threadIdx.x;
    if (j >= total4) return;
    int c = (j & Qmask) * 4;
    float4 v = in[j];
    float a0 = v.x * scale[c]     + shift[c];
    float a1 = v.y * scale[c + 1] + shift[c + 1];
    float a2 = v.z * scale[c + 2] + shift[c + 2];
    float a3 = v.w * scale[c + 3] + shift[c + 3];
    v.x = a0 > 0.f ? a0 : expm1f(a0);
    v.y = a1 > 0.f ? a1 : expm1f(a1);
    v.z = a2 > 0.f ? a2 : expm1f(a2);
    v.w = a3 > 0.f ? a3 : expm1f(a3);
    out[j] = v;
}

// ---------------- final: BN2 + residual + ELU + [N,32]@[32,2] head ----------------
__global__ void finalize_kernel(const float* __restrict__ linW, const float* __restrict__ linb,
                                float* __restrict__ out, int n)
{
    int gw = (blockIdx.x * blockDim.x + threadIdx.x) >> 5;
    int lane = threadIdx.x & 31;
    if (gw >= n) return;
    float v = g_agg2[(size_t)gw * 32 + lane] * g_scale2[lane] + g_shift2[lane]
            + g_res[(size_t)gw * 32 + lane];
    v = v > 0.f ? v : expm1f(v);
    float o0 = v * linW[lane];
    float o1 = v * linW[32 + lane];
    #pragma unroll
    for (int o = 16; o > 0; o >>= 1) {
        o0 += __shfl_xor_sync(0xffffffffu, o0, o);
        o1 += __shfl_xor_sync(0xffffffffu, o1, o);
    }
    if (lane == 0) {
        out[(size_t)gw * 2] = o0 + linb[0];
        out[(size_t)gw * 2 + 1] = o1 + linb[1];
    }
}

// ---------------- host launcher ----------------
extern "C" void kernel_launch(void* const* d_in, const int* in_sizes, int n_in,
                              void* d_out, int out_size)
{
    const float* x      = (const float*)d_in[0];
    const int*   ei     = (const int*)d_in[1];
    const float* Wl1    = (const float*)d_in[2];
    const float* bl1    = (const float*)d_in[3];
    const float* Wr1    = (const float*)d_in[4];
    const float* br1    = (const float*)d_in[5];
    const float* att1   = (const float*)d_in[6];
    const float* bias1  = (const float*)d_in[7];
    const float* Wl2    = (const float*)d_in[8];
    const float* bl2    = (const float*)d_in[9];
    const float* Wr2    = (const float*)d_in[10];
    const float* br2    = (const float*)d_in[11];
    const float* att2   = (const float*)d_in[12];
    const float* bias2  = (const float*)d_in[13];
    const float* bn1_g  = (const float*)d_in[14];
    const float* bn1_b  = (const float*)d_in[15];
    const float* bn2_g  = (const float*)d_in[16];
    const float* bn2_b  = (const float*)d_in[17];
    const float* skipW  = (const float*)d_in[18];
    const float* linW   = (const float*)d_in[19];
    const float* linb   = (const float*)d_in[20];
    float* out = (float*)d_out;

    const int N = in_sizes[0] / 128;
    const int E = in_sizes[1] / 2;
    const int EP = E + N;

    void* p;
    cudaGetSymbolAddress(&p, g_denom1); cudaMemsetAsync(p, 0, (size_t)N * 4 * sizeof(float));
    cudaGetSymbolAddress(&p, g_agg1);   cudaMemsetAsync(p, 0, (size_t)N * 128 * sizeof(float));
    cudaGetSymbolAddress(&p, g_denom2); cudaMemsetAsync(p, 0, (size_t)N * sizeof(float));
    cudaGetSymbolAddress(&p, g_agg2);   cudaMemsetAsync(p, 0, (size_t)N * 32 * sizeof(float));
    cudaGetSymbolAddress(&p, g_sum1);   cudaMemsetAsync(p, 0, 128 * sizeof(double));
    cudaGetSymbolAddress(&p, g_sq1);    cudaMemsetAsync(p, 0, 128 * sizeof(double));
    cudaGetSymbolAddress(&p, g_sum2);   cudaMemsetAsync(p, 0, 32 * sizeof(double));
    cudaGetSymbolAddress(&p, g_sq2);    cudaMemsetAsync(p, 0, 32 * sizeof(double));

    float *d_xl1, *d_xr1, *d_res, *d_h1, *d_xl2, *d_xr2, *d_agg1, *d_agg2;
    float *d_scale1, *d_shift1, *d_scale2, *d_shift2;
    double *d_sum1, *d_sq1, *d_sum2, *d_sq2;
    cudaGetSymbolAddress((void**)&d_xl1, g_xl1);
    cudaGetSymbolAddress((void**)&d_xr1, g_xr1);
    cudaGetSymbolAddress((void**)&d_res, g_res);
    cudaGetSymbolAddress((void**)&d_h1, g_h1);
    cudaGetSymbolAddress((void**)&d_xl2, g_xl2);
    cudaGetSymbolAddress((void**)&d_xr2, g_xr2);
    cudaGetSymbolAddress((void**)&d_agg1, g_agg1);
    cudaGetSymbolAddress((void**)&d_agg2, g_agg2);
    cudaGetSymbolAddress((void**)&d_scale1, g_scale1);
    cudaGetSymbolAddress((void**)&d_shift1, g_shift1);
    cudaGetSymbolAddress((void**)&d_scale2, g_scale2);
    cudaGetSymbolAddress((void**)&d_shift2, g_shift2);
    cudaGetSymbolAddress((void**)&d_sum1, g_sum1);
    cudaGetSymbolAddress((void**)&d_sq1, g_sq1);
    cudaGetSymbolAddress((void**)&d_sum2, g_sum2);
    cudaGetSymbolAddress((void**)&d_sq2, g_sq2);

    const int rowBlocks = (N + 63) / 64;
    const int edgeBlocks = (EP * 32 + 255) / 256;

    transform_kernel<<<dim3(rowBlocks, 5), 256>>>(
        x, N, Wl1, Wr1, skipW, 128, 128, 32,
        bl1, br1, nullptr,
        d_xl1, d_xr1, d_res, 128, 128, 32);

    edge_logits1<<<edgeBlocks, 256>>>(ei, E, N, att1);
    edge_agg1<<<edgeBlocks, 256>>>(ei, E, N);

    bn_stats<128><<<256, 256>>>(d_agg1, bias1, N, d_sum1, d_sq1);
    bn_prep<<<1, 128>>>(d_sum1, d_sq1, N, 128, bn1_g, bn1_b, bias1, d_scale1, d_shift1);
    {
        int total4 = N * 32;  // N*128/4
        bn_apply_elu4<<<(total4 + 255) / 256, 256>>>(
            (const float4*)d_agg1, (float4*)d_h1, total4, 31, d_scale1, d_shift1);
    }

    transform_kernel<<<dim3(rowBlocks, 1), 256>>>(
        d_h1, N, Wl2, Wr2, nullptr, 32, 32, 0,
        bl2, br2, nullptr,
        d_xl2, d_xr2, nullptr, 32, 32, 0);

    edge_logits2<<<edgeBlocks, 256>>>(ei, E, N, att2);
    edge_agg2<<<edgeBlocks, 256>>>(ei, E, N);

    bn_stats<32><<<256, 256>>>(d_agg2, bias2, N, d_sum2, d_sq2);
    bn_prep<<<1, 32>>>(d_sum2, d_sq2, N, 32, bn2_g, bn2_b, bias2, d_scale2, d_shift2);

    finalize_kernel<<<(N * 32 + 255) / 256, 256>>>(linW, linb, out, N);
}

// round 4
// speedup vs baseline: 1.4612x; 1.3037x over previous
#include <cuda_runtime.h>
#include <math.h>

#define MAXN 50000
#define MAXE 800000
#define MAXEP (MAXN + MAXE)

// ---------------- scratch (device globals; no allocation allowed) ----------------
__device__ float g_xl1[MAXN * 128];
__device__ float g_xr1[MAXN * 128];
__device__ float g_res[MAXN * 32];
__device__ float g_denom1[MAXN * 4];
__device__ float g_agg1[MAXN * 128];
__device__ float g_xl2[MAXN * 32];
__device__ float g_xr2[MAXN * 32];
__device__ float g_denom2[MAXN];
__device__ float g_agg2[MAXN * 32];
__device__ double g_sum1[128], g_sq1[128];
__device__ double g_sum2[32], g_sq2[32];
__device__ float g_scale1[128], g_shift1[128];
__device__ float g_scale2[32], g_shift2[32];

// vector reduction (no-return atomic add), sm_90+
__device__ __forceinline__ void red_add_f4(float* addr, float4 v) {
    asm volatile("red.global.add.v4.f32 [%0], {%1,%2,%3,%4};"
                 :: "l"(addr), "f"(v.x), "f"(v.y), "f"(v.z), "f"(v.w)
                 : "memory");
}

// ---------------- fused dense transform: out = X @ W^T (+bias), K=128 ----------------
// Optional input normalization: when norm_den != nullptr, the X element at
// (row, c) is first mapped  v -> elu( v/(den[row,head(c)]+1e-16) * nscale[c] + nshift[c] )
// where head(c) = c>>5 (conv1 output layout: 4 heads x 32 ch).
__global__ void transform_kernel(
    const float* __restrict__ X, int n,
    const float* __restrict__ W0, const float* __restrict__ W1, const float* __restrict__ W2,
    int F0, int F1, int F2,
    const float* __restrict__ b0, const float* __restrict__ b1, const float* __restrict__ b2,
    float* __restrict__ o0, float* __restrict__ o1, float* __restrict__ o2,
    int ld0, int ld1, int ld2,
    const float* __restrict__ norm_den,
    const float* __restrict__ nscale,
    const float* __restrict__ nshift)
{
    __shared__ float Xs[64][68];
    __shared__ float Ws[64][68];
    const int rb = blockIdx.x * 64;
    const int fb = blockIdx.y * 64;
    const int tid = threadIdx.x;
    const int Ft = F0 + F1 + F2;

    const int tx = tid & 15, ty = tid >> 4;
    float acc[4][4];
    #pragma unroll
    for (int i = 0; i < 4; i++)
        #pragma unroll
        for (int j = 0; j < 4; j++) acc[i][j] = 0.f;

    for (int kk = 0; kk < 128; kk += 64) {
        #pragma unroll
        for (int it = 0; it < 4; it++) {
            int idx = it * 256 + tid;
            int r = idx >> 4;
            int kc = (idx & 15) << 2;
            float4 v = make_float4(0.f, 0.f, 0.f, 0.f);
            int row = rb + r;
            if (row < n) {
                int c = kk + kc;
                v = *(const float4*)(X + (size_t)row * 128 + c);
                if (norm_den) {
                    float den = norm_den[(size_t)row * 4 + (c >> 5)] + 1e-16f;
                    float inv = __fdividef(1.f, den);
                    float4 sc = *(const float4*)(nscale + c);
                    float4 sh = *(const float4*)(nshift + c);
                    float a0 = v.x * inv * sc.x + sh.x;
                    float a1 = v.y * inv * sc.y + sh.y;
                    float a2 = v.z * inv * sc.z + sh.z;
                    float a3 = v.w * inv * sc.w + sh.w;
                    v.x = a0 > 0.f ? a0 : expm1f(a0);
                    v.y = a1 > 0.f ? a1 : expm1f(a1);
                    v.z = a2 > 0.f ? a2 : expm1f(a2);
                    v.w = a3 > 0.f ? a3 : expm1f(a3);
                }
            }
            Xs[r][kc] = v.x; Xs[r][kc + 1] = v.y; Xs[r][kc + 2] = v.z; Xs[r][kc + 3] = v.w;
        }
        #pragma unroll
        for (int it = 0; it < 4; it++) {
            int idx = it * 256 + tid;
            int f = idx >> 4;
            int kc = (idx & 15) << 2;
            int gf = fb + f;
            float4 v = make_float4(0.f, 0.f, 0.f, 0.f);
            const float* Wp = nullptr;
            int lf = gf;
            if (gf < F0) { Wp = W0; }
            else if (gf < F0 + F1) { Wp = W1; lf = gf - F0; }
            else if (gf < Ft) { Wp = W2; lf = gf - F0 - F1; }
            if (Wp) v = *(const float4*)(Wp + (size_t)lf * 128 + kk + kc);
            Ws[f][kc] = v.x; Ws[f][kc + 1] = v.y; Ws[f][kc + 2] = v.z; Ws[f][kc + 3] = v.w;
        }
        __syncthreads();

        #pragma unroll 8
        for (int k = 0; k < 64; k++) {
            float a[4], b[4];
            #pragma unroll
            for (int i = 0; i < 4; i++) a[i] = Xs[ty * 4 + i][k];
            #pragma unroll
            for (int j = 0; j < 4; j++) b[j] = Ws[tx * 4 + j][k];
            #pragma unroll
            for (int i = 0; i < 4; i++)
                #pragma unroll
                for (int j = 0; j < 4; j++) acc[i][j] += a[i] * b[j];
        }
        __syncthreads();
    }

    #pragma unroll
    for (int i = 0; i < 4; i++) {
        int row = rb + ty * 4 + i;
        if (row >= n) break;
        #pragma unroll
        for (int j = 0; j < 4; j++) {
            int gf = fb + tx * 4 + j;
            if (gf < F0) {
                float bb = b0 ? b0[gf] : 0.f;
                o0[(size_t)row * ld0 + gf] = acc[i][j] + bb;
            } else if (gf < F0 + F1) {
                int lf = gf - F0;
                float bb = b1 ? b1[lf] : 0.f;
                o1[(size_t)row * ld1 + lf] = acc[i][j] + bb;
            } else if (gf < Ft) {
                int lf = gf - F0 - F1;
                float bb = b2 ? b2[lf] : 0.f;
                o2[(size_t)row * ld2 + lf] = acc[i][j] + bb;
            }
        }
    }
}

// ---------------- conv1 fused edge pass: logits -> exp -> scatter a*xl and a ----------------
// warp per edge; lane loads float4 of features [4*lane, 4*lane+4); head = lane>>3.
// Scatters UNNORMALIZED a*xl into agg1 and a into denom1; normalization happens
// at the node level downstream (bn_stats / transform2 input load).
__global__ void edge_fused1(const int* __restrict__ ei, int E, int N,
                            const float* __restrict__ att)
{
    int gw = (blockIdx.x * blockDim.x + threadIdx.x) >> 5;
    int lane = threadIdx.x & 31;
    int EP = E + N;
    if (gw >= EP) return;
    int s, d;
    if (gw < E) { s = ei[gw]; d = ei[E + gw]; }
    else { s = gw - E; d = s; }

    float4 xl = *(const float4*)(g_xl1 + (size_t)s * 128 + lane * 4);
    float4 xr = *(const float4*)(g_xr1 + (size_t)d * 128 + lane * 4);
    float4 at = *(const float4*)(att + lane * 4);
    float m0 = xl.x + xr.x, m1 = xl.y + xr.y, m2 = xl.z + xr.z, m3 = xl.w + xr.w;
    float l = (m0 > 0.f ? m0 : 0.2f * m0) * at.x
            + (m1 > 0.f ? m1 : 0.2f * m1) * at.y
            + (m2 > 0.f ? m2 : 0.2f * m2) * at.z
            + (m3 > 0.f ? m3 : 0.2f * m3) * at.w;
    // butterfly within 8-lane groups (same head): all 8 lanes end with the head logit
    l += __shfl_xor_sync(0xffffffffu, l, 1);
    l += __shfl_xor_sync(0xffffffffu, l, 2);
    l += __shfl_xor_sync(0xffffffffu, l, 4);
    float a = expf(l);
    xl.x *= a; xl.y *= a; xl.z *= a; xl.w *= a;
    red_add_f4(g_agg1 + (size_t)d * 128 + lane * 4, xl);
    if ((lane & 7) == 0)
        atomicAdd(&g_denom1[(size_t)d * 4 + (lane >> 3)], a);
}

// ---------------- conv2 fused edge pass ----------------
__global__ void edge_fused2(const int* __restrict__ ei, int E, int N,
                            const float* __restrict__ att)
{
    int gw = (blockIdx.x * blockDim.x + threadIdx.x) >> 5;
    int lane = threadIdx.x & 31;
    int EP = E + N;
    if (gw >= EP) return;
    int s, d;
    if (gw < E) { s = ei[gw]; d = ei[E + gw]; }
    else { s = gw - E; d = s; }

    float m = g_xl2[(size_t)s * 32 + lane] + g_xr2[(size_t)d * 32 + lane];
    float e = m > 0.f ? m : 0.2f * m;
    float l = e * att[lane];
    #pragma unroll
    for (int o = 16; o > 0; o >>= 1) l += __shfl_xor_sync(0xffffffffu, l, o);
    float a = expf(l);
    if (lane < 8) {
        float4 v = *(const float4*)(g_xl2 + (size_t)s * 32 + lane * 4);
        v.x *= a; v.y *= a; v.z *= a; v.w *= a;
        red_add_f4(g_agg2 + (size_t)d * 32 + lane * 4, v);
    }
    if (lane == 0) atomicAdd(&g_denom2[d], a);
}

// ---------------- batch-norm statistics over NORMALIZED values ----------------
// v = agg/(den+1e-16) + bias.  HEADS=4: den idx = row*4 + (q>>3); HEADS=1: den idx = row.
template <int C, int HEADS>
__global__ void bn_stats(const float* __restrict__ h, const float* __restrict__ den,
                         const float* __restrict__ bias,
                         int n, double* __restrict__ sum, double* __restrict__ sq)
{
    const int Q = C / 4;
    int tid = threadIdx.x;
    int q = tid & (Q - 1);
    float4 bc = *(const float4*)(bias + q * 4);
    float s0 = 0.f, s1 = 0.f, s2v = 0.f, s3 = 0.f;
    float t0 = 0.f, t1 = 0.f, t2 = 0.f, t3 = 0.f;
    size_t total4 = (size_t)n * Q;
    const float4* h4 = (const float4*)h;
    for (size_t j = (size_t)blockIdx.x * blockDim.x + tid; j < total4;
         j += (size_t)gridDim.x * blockDim.x) {
        float4 v = h4[j];
        size_t row = j / Q;
        float dd = (HEADS == 4) ? den[row * 4 + (q >> 3)] : den[row];
        float inv = __fdividef(1.f, dd + 1e-16f);
        float a0 = v.x * inv + bc.x, a1 = v.y * inv + bc.y;
        float a2 = v.z * inv + bc.z, a3 = v.w * inv + bc.w;
        s0 += a0; t0 += a0 * a0;
        s1 += a1; t1 += a1 * a1;
        s2v += a2; t2 += a2 * a2;
        s3 += a3; t3 += a3 * a3;
    }
    __shared__ float red[8][256];
    red[0][tid] = s0; red[1][tid] = s1; red[2][tid] = s2v; red[3][tid] = s3;
    red[4][tid] = t0; red[5][tid] = t1; red[6][tid] = t2; red[7][tid] = t3;
    __syncthreads();
    if (tid < Q) {
        const int G = 256 / Q;
        #pragma unroll
        for (int k = 0; k < 8; k++) {
            float acc = 0.f;
            for (int r = 0; r < G; r++) acc += red[k][tid + r * Q];
            if (k < 4) atomicAdd(&sum[tid * 4 + k], (double)acc);
            else       atomicAdd(&sq[tid * 4 + (k - 4)], (double)acc);
        }
    }
}

__global__ void bn_prep(const double* __restrict__ sum, const double* __restrict__ sq,
                        int n, int C,
                        const float* __restrict__ g, const float* __restrict__ b,
                        const float* __restrict__ bias,
                        float* __restrict__ scale, float* __restrict__ shift)
{
    int c = threadIdx.x;
    if (c >= C) return;
    double mu = sum[c] / n;
    double var = sq[c] / n - mu * mu;
    float istd = rsqrtf((float)var + 1e-5f);
    float sc = istd * g[c];
    scale[c] = sc;
    shift[c] = (bias[c] - (float)mu) * sc + b[c];
}

// ---------------- final: normalize + BN2 + residual + ELU + [N,32]@[32,2] head ----------------
__global__ void finalize_kernel(const float* __restrict__ linW, const float* __restrict__ linb,
                                float* __restrict__ out, int n)
{
    int gw = (blockIdx.x * blockDim.x + threadIdx.x) >> 5;
    int lane = threadIdx.x & 31;
    if (gw >= n) return;
    float inv = __fdividef(1.f, g_denom2[gw] + 1e-16f);
    float v = g_agg2[(size_t)gw * 32 + lane] * inv * g_scale2[lane] + g_shift2[lane]
            + g_res[(size_t)gw * 32 + lane];
    v = v > 0.f ? v : expm1f(v);
    float o0 = v * linW[lane];
    float o1 = v * linW[32 + lane];
    #pragma unroll
    for (int o = 16; o > 0; o >>= 1) {
        o0 += __shfl_xor_sync(0xffffffffu, o0, o);
        o1 += __shfl_xor_sync(0xffffffffu, o1, o);
    }
    if (lane == 0) {
        out[(size_t)gw * 2] = o0 + linb[0];
        out[(size_t)gw * 2 + 1] = o1 + linb[1];
    }
}

// ---------------- host launcher ----------------
extern "C" void kernel_launch(void* const* d_in, const int* in_sizes, int n_in,
                              void* d_out, int out_size)
{
    const float* x      = (const float*)d_in[0];
    const int*   ei     = (const int*)d_in[1];
    const float* Wl1    = (const float*)d_in[2];
    const float* bl1    = (const float*)d_in[3];
    const float* Wr1    = (const float*)d_in[4];
    const float* br1    = (const float*)d_in[5];
    const float* att1   = (const float*)d_in[6];
    const float* bias1  = (const float*)d_in[7];
    const float* Wl2    = (const float*)d_in[8];
    const float* bl2    = (const float*)d_in[9];
    const float* Wr2    = (const float*)d_in[10];
    const float* br2    = (const float*)d_in[11];
    const float* att2   = (const float*)d_in[12];
    const float* bias2  = (const float*)d_in[13];
    const float* bn1_g  = (const float*)d_in[14];
    const float* bn1_b  = (const float*)d_in[15];
    const float* bn2_g  = (const float*)d_in[16];
    const float* bn2_b  = (const float*)d_in[17];
    const float* skipW  = (const float*)d_in[18];
    const float* linW   = (const float*)d_in[19];
    const float* linb   = (const float*)d_in[20];
    float* out = (float*)d_out;

    const int N = in_sizes[0] / 128;
    const int E = in_sizes[1] / 2;
    const int EP = E + N;

    void* p;
    cudaGetSymbolAddress(&p, g_denom1); cudaMemsetAsync(p, 0, (size_t)N * 4 * sizeof(float));
    cudaGetSymbolAddress(&p, g_agg1);   cudaMemsetAsync(p, 0, (size_t)N * 128 * sizeof(float));
    cudaGetSymbolAddress(&p, g_denom2); cudaMemsetAsync(p, 0, (size_t)N * sizeof(float));
    cudaGetSymbolAddress(&p, g_agg2);   cudaMemsetAsync(p, 0, (size_t)N * 32 * sizeof(float));
    cudaGetSymbolAddress(&p, g_sum1);   cudaMemsetAsync(p, 0, 128 * sizeof(double));
    cudaGetSymbolAddress(&p, g_sq1);    cudaMemsetAsync(p, 0, 128 * sizeof(double));
    cudaGetSymbolAddress(&p, g_sum2);   cudaMemsetAsync(p, 0, 32 * sizeof(double));
    cudaGetSymbolAddress(&p, g_sq2);    cudaMemsetAsync(p, 0, 32 * sizeof(double));

    float *d_xl1, *d_xr1, *d_res, *d_xl2, *d_xr2, *d_agg1, *d_agg2, *d_den1;
    float *d_scale1, *d_shift1, *d_scale2, *d_shift2;
    double *d_sum1, *d_sq1, *d_sum2, *d_sq2;
    float *d_den2;
    cudaGetSymbolAddress((void**)&d_xl1, g_xl1);
    cudaGetSymbolAddress((void**)&d_xr1, g_xr1);
    cudaGetSymbolAddress((void**)&d_res, g_res);
    cudaGetSymbolAddress((void**)&d_xl2, g_xl2);
    cudaGetSymbolAddress((void**)&d_xr2, g_xr2);
    cudaGetSymbolAddress((void**)&d_agg1, g_agg1);
    cudaGetSymbolAddress((void**)&d_agg2, g_agg2);
    cudaGetSymbolAddress((void**)&d_den1, g_denom1);
    cudaGetSymbolAddress((void**)&d_den2, g_denom2);
    cudaGetSymbolAddress((void**)&d_scale1, g_scale1);
    cudaGetSymbolAddress((void**)&d_shift1, g_shift1);
    cudaGetSymbolAddress((void**)&d_scale2, g_scale2);
    cudaGetSymbolAddress((void**)&d_shift2, g_shift2);
    cudaGetSymbolAddress((void**)&d_sum1, g_sum1);
    cudaGetSymbolAddress((void**)&d_sq1, g_sq1);
    cudaGetSymbolAddress((void**)&d_sum2, g_sum2);
    cudaGetSymbolAddress((void**)&d_sq2, g_sq2);

    const int rowBlocks = (N + 63) / 64;
    const int edgeBlocks = (EP * 32 + 255) / 256;

    // conv1 transforms + residual: 288 features = Wl1(128) | Wr1(128) | skip(32)
    transform_kernel<<<dim3(rowBlocks, 5), 256>>>(
        x, N, Wl1, Wr1, skipW, 128, 128, 32,
        bl1, br1, nullptr,
        d_xl1, d_xr1, d_res, 128, 128, 32,
        nullptr, nullptr, nullptr);

    edge_fused1<<<edgeBlocks, 256>>>(ei, E, N, att1);

    bn_stats<128, 4><<<256, 256>>>(d_agg1, d_den1, bias1, N, d_sum1, d_sq1);
    bn_prep<<<1, 128>>>(d_sum1, d_sq1, N, 128, bn1_g, bn1_b, bias1, d_scale1, d_shift1);

    // conv2 transforms reading agg1 with on-the-fly normalize + BN + ELU
    transform_kernel<<<dim3(rowBlocks, 1), 256>>>(
        d_agg1, N, Wl2, Wr2, nullptr, 32, 32, 0,
        bl2, br2, nullptr,
        d_xl2, d_xr2, nullptr, 32, 32, 0,
        d_den1, d_scale1, d_shift1);

    edge_fused2<<<edgeBlocks, 256>>>(ei, E, N, att2);

    bn_stats<32, 1><<<256, 256>>>(d_agg2, d_den2, bias2, N, d_sum2, d_sq2);
    bn_prep<<<1, 32>>>(d_sum2, d_sq2, N, 32, bn2_g, bn2_b, bias2, d_scale2, d_shift2);

    finalize_kernel<<<(N * 32 + 255) / 256, 256>>>(linW, linb, out, N);
}

// round 5
// speedup vs baseline: 1.7710x; 1.2120x over previous
#include <cuda_runtime.h>
#include <math.h>

#define MAXN 50000
#define MAXE 800000
#define MAXEP (MAXN + MAXE)

// ---------------- scratch (device globals; no allocation allowed) ----------------
__device__ float g_xl1[MAXN * 128];
__device__ float g_xr1[MAXN * 128];
__device__ float g_res[MAXN * 32];
__device__ float g_agg1[MAXN * 128];   // normalized conv1 output (pre-bias)
__device__ float g_xl2[MAXN * 32];
__device__ float g_xr2[MAXN * 32];
__device__ float g_agg2[MAXN * 32];    // normalized conv2 output (pre-bias)
__device__ double g_sum1[128], g_sq1[128];
__device__ double g_sum2[32], g_sq2[32];
__device__ float g_scale1[128], g_shift1[128];
__device__ float g_scale2[32], g_shift2[32];
// CSR-by-destination
__device__ int g_count[MAXN];
__device__ int g_off[MAXN + 1];
__device__ int g_cursor[MAXN];
__device__ int g_bsum[128];
__device__ int g_csr[MAXEP];

// ---------------- CSR build ----------------
__global__ void csr_init(int N) {
    int i = blockIdx.x * blockDim.x + threadIdx.x;
    if (i < N) g_count[i] = 1;   // self-loop
}

__global__ void csr_hist(const int* __restrict__ ei, int E) {
    int e = blockIdx.x * blockDim.x + threadIdx.x;
    if (e < E) atomicAdd(&g_count[ei[E + e]], 1);
}

// block-wise exclusive scan of counts -> g_off (local), block totals -> g_bsum
__global__ void csr_scan1(int N) {
    __shared__ int sh[512];
    int tid = threadIdx.x;
    int i = blockIdx.x * 512 + tid;
    int v = (i < N) ? g_count[i] : 0;
    sh[tid] = v;
    __syncthreads();
    for (int ofs = 1; ofs < 512; ofs <<= 1) {
        int t = (tid >= ofs) ? sh[tid - ofs] : 0;
        __syncthreads();
        sh[tid] += t;
        __syncthreads();
    }
    if (i < N) g_off[i] = sh[tid] - v;
    if (tid == 511) g_bsum[blockIdx.x] = sh[511];
}

// single-block exclusive scan over block sums (nb <= 128)
__global__ void csr_scan2(int nb) {
    __shared__ int sh[128];
    int tid = threadIdx.x;
    int v = (tid < nb) ? g_bsum[tid] : 0;
    sh[tid] = v;
    __syncthreads();
    for (int ofs = 1; ofs < 128; ofs <<= 1) {
        int t = (tid >= ofs) ? sh[tid - ofs] : 0;
        __syncthreads();
        sh[tid] += t;
        __syncthreads();
    }
    if (tid < nb) g_bsum[tid] = sh[tid] - v;
}

__global__ void csr_scan3(int N, int EP) {
    int i = blockIdx.x * blockDim.x + threadIdx.x;
    if (i < N) {
        int o = g_off[i] + g_bsum[i >> 9];
        g_off[i] = o;
        g_cursor[i] = o;
    }
    if (i == 0) g_off[N] = EP;
}

__global__ void csr_scatter(const int* __restrict__ ei, int E, int N) {
    int e = blockIdx.x * blockDim.x + threadIdx.x;
    int EP = E + N;
    if (e >= EP) return;
    int s, d;
    if (e < E) { s = ei[e]; d = ei[E + e]; }
    else { s = e - E; d = s; }
    int pos = atomicAdd(&g_cursor[d], 1);
    g_csr[pos] = s;
}

// ---------------- fused dense transform: out = X @ W^T (+bias), K=128 ----------------
// Optional input transform: when nscale != nullptr, X element at (row,c) is
// mapped  v -> elu(v * nscale[c] + nshift[c])  (input already normalized).
__global__ void transform_kernel(
    const float* __restrict__ X, int n,
    const float* __restrict__ W0, const float* __restrict__ W1, const float* __restrict__ W2,
    int F0, int F1, int F2,
    const float* __restrict__ b0, const float* __restrict__ b1, const float* __restrict__ b2,
    float* __restrict__ o0, float* __restrict__ o1, float* __restrict__ o2,
    int ld0, int ld1, int ld2,
    const float* __restrict__ nscale,
    const float* __restrict__ nshift)
{
    __shared__ float Xs[64][68];
    __shared__ float Ws[64][68];
    const int rb = blockIdx.x * 64;
    const int fb = blockIdx.y * 64;
    const int tid = threadIdx.x;
    const int Ft = F0 + F1 + F2;

    const int tx = tid & 15, ty = tid >> 4;
    float acc[4][4];
    #pragma unroll
    for (int i = 0; i < 4; i++)
        #pragma unroll
        for (int j = 0; j < 4; j++) acc[i][j] = 0.f;

    for (int kk = 0; kk < 128; kk += 64) {
        #pragma unroll
        for (int it = 0; it < 4; it++) {
            int idx = it * 256 + tid;
            int r = idx >> 4;
            int kc = (idx & 15) << 2;
            float4 v = make_float4(0.f, 0.f, 0.f, 0.f);
            int row = rb + r;
            if (row < n) {
                int c = kk + kc;
                v = *(const float4*)(X + (size_t)row * 128 + c);
                if (nscale) {
                    float4 sc = *(const float4*)(nscale + c);
                    float4 sh = *(const float4*)(nshift + c);
                    float a0 = v.x * sc.x + sh.x;
                    float a1 = v.y * sc.y + sh.y;
                    float a2 = v.z * sc.z + sh.z;
                    float a3 = v.w * sc.w + sh.w;
                    v.x = a0 > 0.f ? a0 : expm1f(a0);
                    v.y = a1 > 0.f ? a1 : expm1f(a1);
                    v.z = a2 > 0.f ? a2 : expm1f(a2);
                    v.w = a3 > 0.f ? a3 : expm1f(a3);
                }
            }
            Xs[r][kc] = v.x; Xs[r][kc + 1] = v.y; Xs[r][kc + 2] = v.z; Xs[r][kc + 3] = v.w;
        }
        #pragma unroll
        for (int it = 0; it < 4; it++) {
            int idx = it * 256 + tid;
            int f = idx >> 4;
            int kc = (idx & 15) << 2;
            int gf = fb + f;
            float4 v = make_float4(0.f, 0.f, 0.f, 0.f);
            const float* Wp = nullptr;
            int lf = gf;
            if (gf < F0) { Wp = W0; }
            else if (gf < F0 + F1) { Wp = W1; lf = gf - F0; }
            else if (gf < Ft) { Wp = W2; lf = gf - F0 - F1; }
            if (Wp) v = *(const float4*)(Wp + (size_t)lf * 128 + kk + kc);
            Ws[f][kc] = v.x; Ws[f][kc + 1] = v.y; Ws[f][kc + 2] = v.z; Ws[f][kc + 3] = v.w;
        }
        __syncthreads();

        #pragma unroll 8
        for (int k = 0; k < 64; k++) {
            float a[4], b[4];
            #pragma unroll
            for (int i = 0; i < 4; i++) a[i] = Xs[ty * 4 + i][k];
            #pragma unroll
            for (int j = 0; j < 4; j++) b[j] = Ws[tx * 4 + j][k];
            #pragma unroll
            for (int i = 0; i < 4; i++)
                #pragma unroll
                for (int j = 0; j < 4; j++) acc[i][j] += a[i] * b[j];
        }
        __syncthreads();
    }

    #pragma unroll
    for (int i = 0; i < 4; i++) {
        int row = rb + ty * 4 + i;
        if (row >= n) break;
        #pragma unroll
        for (int j = 0; j < 4; j++) {
            int gf = fb + tx * 4 + j;
            if (gf < F0) {
                float bb = b0 ? b0[gf] : 0.f;
                o0[(size_t)row * ld0 + gf] = acc[i][j] + bb;
            } else if (gf < F0 + F1) {
                int lf = gf - F0;
                float bb = b1 ? b1[lf] : 0.f;
                o1[(size_t)row * ld1 + lf] = acc[i][j] + bb;
            } else if (gf < Ft) {
                int lf = gf - F0 - F1;
                float bb = b2 ? b2[lf] : 0.f;
                o2[(size_t)row * ld2 + lf] = acc[i][j] + bb;
            }
        }
    }
}

// ---------------- conv1 aggregation: warp per destination node ----------------
// lane owns float4 of features [4*lane, 4*lane+4); head = lane>>3.
// Output stored NORMALIZED (softmax applied), no bias.
__global__ void agg_conv1(int N, const float* __restrict__ att)
{
    int w = (blockIdx.x * blockDim.x + threadIdx.x) >> 5;
    int lane = threadIdx.x & 31;
    if (w >= N) return;
    int beg = g_off[w], end = g_off[w + 1];

    float4 xr = *(const float4*)(g_xr1 + (size_t)w * 128 + lane * 4);
    float4 at = *(const float4*)(att + lane * 4);
    float4 acc = make_float4(0.f, 0.f, 0.f, 0.f);
    float den = 0.f;

    for (int j = beg; j < end; j++) {
        int s = g_csr[j];
        float4 xl = *(const float4*)(g_xl1 + (size_t)s * 128 + lane * 4);
        float m0 = xl.x + xr.x, m1 = xl.y + xr.y, m2 = xl.z + xr.z, m3 = xl.w + xr.w;
        float l = (m0 > 0.f ? m0 : 0.2f * m0) * at.x
                + (m1 > 0.f ? m1 : 0.2f * m1) * at.y
                + (m2 > 0.f ? m2 : 0.2f * m2) * at.z
                + (m3 > 0.f ? m3 : 0.2f * m3) * at.w;
        // butterfly within 8-lane head group: all lanes get the head logit
        l += __shfl_xor_sync(0xffffffffu, l, 1);
        l += __shfl_xor_sync(0xffffffffu, l, 2);
        l += __shfl_xor_sync(0xffffffffu, l, 4);
        float a = expf(l);
        acc.x += a * xl.x; acc.y += a * xl.y; acc.z += a * xl.z; acc.w += a * xl.w;
        den += a;
    }
    float inv = __fdividef(1.f, den + 1e-16f);
    acc.x *= inv; acc.y *= inv; acc.z *= inv; acc.w *= inv;
    *(float4*)(g_agg1 + (size_t)w * 128 + lane * 4) = acc;
}

// ---------------- conv2 aggregation: warp per destination node, 1 ch/lane ----------------
__global__ void agg_conv2(int N, const float* __restrict__ att)
{
    int w = (blockIdx.x * blockDim.x + threadIdx.x) >> 5;
    int lane = threadIdx.x & 31;
    if (w >= N) return;
    int beg = g_off[w], end = g_off[w + 1];

    float xr = g_xr2[(size_t)w * 32 + lane];
    float attc = att[lane];
    float acc = 0.f, den = 0.f;

    for (int j = beg; j < end; j++) {
        int s = g_csr[j];
        float xl = g_xl2[(size_t)s * 32 + lane];
        float m = xl + xr;
        float l = (m > 0.f ? m : 0.2f * m) * attc;
        #pragma unroll
        for (int o = 16; o > 0; o >>= 1) l += __shfl_xor_sync(0xffffffffu, l, o);
        float a = expf(l);
        acc += a * xl;
        den += a;
    }
    g_agg2[(size_t)w * 32 + lane] = acc * __fdividef(1.f, den + 1e-16f);
}

// ---------------- batch-norm statistics over (normalized agg + bias) ----------------
template <int C>
__global__ void bn_stats(const float* __restrict__ h, const float* __restrict__ bias,
                         int n, double* __restrict__ sum, double* __restrict__ sq)
{
    const int Q = C / 4;
    int tid = threadIdx.x;
    int q = tid & (Q - 1);
    float4 bc = *(const float4*)(bias + q * 4);
    float s0 = 0.f, s1 = 0.f, s2v = 0.f, s3 = 0.f;
    float t0 = 0.f, t1 = 0.f, t2 = 0.f, t3 = 0.f;
    size_t total4 = (size_t)n * Q;
    const float4* h4 = (const float4*)h;
    for (size_t j = (size_t)blockIdx.x * blockDim.x + tid; j < total4;
         j += (size_t)gridDim.x * blockDim.x) {
        float4 v = h4[j];
        float a0 = v.x + bc.x, a1 = v.y + bc.y, a2 = v.z + bc.z, a3 = v.w + bc.w;
        s0 += a0; t0 += a0 * a0;
        s1 += a1; t1 += a1 * a1;
        s2v += a2; t2 += a2 * a2;
        s3 += a3; t3 += a3 * a3;
    }
    __shared__ float red[8][256];
    red[0][tid] = s0; red[1][tid] = s1; red[2][tid] = s2v; red[3][tid] = s3;
    red[4][tid] = t0; red[5][tid] = t1; red[6][tid] = t2; red[7][tid] = t3;
    __syncthreads();
    if (tid < Q) {
        const int G = 256 / Q;
        #pragma unroll
        for (int k = 0; k < 8; k++) {
            float acc = 0.f;
            for (int r = 0; r < G; r++) acc += red[k][tid + r * Q];
            if (k < 4) atomicAdd(&sum[tid * 4 + k], (double)acc);
            else       atomicAdd(&sq[tid * 4 + (k - 4)], (double)acc);
        }
    }
}

__global__ void bn_prep(const double* __restrict__ sum, const double* __restrict__ sq,
                        int n, int C,
                        const float* __restrict__ g, const float* __restrict__ b,
                        const float* __restrict__ bias,
                        float* __restrict__ scale, float* __restrict__ shift)
{
    int c = threadIdx.x;
    if (c >= C) return;
    double mu = sum[c] / n;
    double var = sq[c] / n - mu * mu;
    float istd = rsqrtf((float)var + 1e-5f);
    float sc = istd * g[c];
    scale[c] = sc;
    shift[c] = (bias[c] - (float)mu) * sc + b[c];
}

// ---------------- final: BN2 + residual + ELU + [N,32]@[32,2] head ----------------
__global__ void finalize_kernel(const float* __restrict__ linW, const float* __restrict__ linb,
                                float* __restrict__ out, int n)
{
    int gw = (blockIdx.x * blockDim.x + threadIdx.x) >> 5;
    int lane = threadIdx.x & 31;
    if (gw >= n) return;
    float v = g_agg2[(size_t)gw * 32 + lane] * g_scale2[lane] + g_shift2[lane]
            + g_res[(size_t)gw * 32 + lane];
    v = v > 0.f ? v : expm1f(v);
    float o0 = v * linW[lane];
    float o1 = v * linW[32 + lane];
    #pragma unroll
    for (int o = 16; o > 0; o >>= 1) {
        o0 += __shfl_xor_sync(0xffffffffu, o0, o);
        o1 += __shfl_xor_sync(0xffffffffu, o1, o);
    }
    if (lane == 0) {
        out[(size_t)gw * 2] = o0 + linb[0];
        out[(size_t)gw * 2 + 1] = o1 + linb[1];
    }
}

// ---------------- host launcher ----------------
extern "C" void kernel_launch(void* const* d_in, const int* in_sizes, int n_in,
                              void* d_out, int out_size)
{
    const float* x      = (const float*)d_in[0];
    const int*   ei     = (const int*)d_in[1];
    const float* Wl1    = (const float*)d_in[2];
    const float* bl1    = (const float*)d_in[3];
    const float* Wr1    = (const float*)d_in[4];
    const float* br1    = (const float*)d_in[5];
    const float* att1   = (const float*)d_in[6];
    const float* bias1  = (const float*)d_in[7];
    const float* Wl2    = (const float*)d_in[8];
    const float* bl2    = (const float*)d_in[9];
    const float* Wr2    = (const float*)d_in[10];
    const float* br2    = (const float*)d_in[11];
    const float* att2   = (const float*)d_in[12];
    const float* bias2  = (const float*)d_in[13];
    const float* bn1_g  = (const float*)d_in[14];
    const float* bn1_b  = (const float*)d_in[15];
    const float* bn2_g  = (const float*)d_in[16];
    const float* bn2_b  = (const float*)d_in[17];
    const float* skipW  = (const float*)d_in[18];
    const float* linW   = (const float*)d_in[19];
    const float* linb   = (const float*)d_in[20];
    float* out = (float*)d_out;

    const int N = in_sizes[0] / 128;
    const int E = in_sizes[1] / 2;
    const int EP = E + N;

    void* p;
    cudaGetSymbolAddress(&p, g_sum1); cudaMemsetAsync(p, 0, 128 * sizeof(double));
    cudaGetSymbolAddress(&p, g_sq1);  cudaMemsetAsync(p, 0, 128 * sizeof(double));
    cudaGetSymbolAddress(&p, g_sum2); cudaMemsetAsync(p, 0, 32 * sizeof(double));
    cudaGetSymbolAddress(&p, g_sq2);  cudaMemsetAsync(p, 0, 32 * sizeof(double));

    float *d_xl1, *d_xr1, *d_res, *d_xl2, *d_xr2, *d_agg1, *d_agg2;
    float *d_scale1, *d_shift1, *d_scale2, *d_shift2;
    double *d_sum1, *d_sq1, *d_sum2, *d_sq2;
    cudaGetSymbolAddress((void**)&d_xl1, g_xl1);
    cudaGetSymbolAddress((void**)&d_xr1, g_xr1);
    cudaGetSymbolAddress((void**)&d_res, g_res);
    cudaGetSymbolAddress((void**)&d_xl2, g_xl2);
    cudaGetSymbolAddress((void**)&d_xr2, g_xr2);
    cudaGetSymbolAddress((void**)&d_agg1, g_agg1);
    cudaGetSymbolAddress((void**)&d_agg2, g_agg2);
    cudaGetSymbolAddress((void**)&d_scale1, g_scale1);
    cudaGetSymbolAddress((void**)&d_shift1, g_shift1);
    cudaGetSymbolAddress((void**)&d_scale2, g_scale2);
    cudaGetSymbolAddress((void**)&d_shift2, g_shift2);
    cudaGetSymbolAddress((void**)&d_sum1, g_sum1);
    cudaGetSymbolAddress((void**)&d_sq1, g_sq1);
    cudaGetSymbolAddress((void**)&d_sum2, g_sum2);
    cudaGetSymbolAddress((void**)&d_sq2, g_sq2);

    const int rowBlocks = (N + 63) / 64;
    const int nodeWarpBlocks = (N * 32 + 255) / 256;
    const int nbScan = (N + 511) / 512;

    // ---- CSR build (depends only on ei) ----
    csr_init<<<(N + 255) / 256, 256>>>(N);
    csr_hist<<<(E + 255) / 256, 256>>>(ei, E);
    csr_scan1<<<nbScan, 512>>>(N);
    csr_scan2<<<1, 128>>>(nbScan);
    csr_scan3<<<(N + 255) / 256, 256>>>(N, EP);
    csr_scatter<<<(EP + 255) / 256, 256>>>(ei, E, N);

    // conv1 transforms + residual: 288 features = Wl1(128) | Wr1(128) | skip(32)
    transform_kernel<<<dim3(rowBlocks, 5), 256>>>(
        x, N, Wl1, Wr1, skipW, 128, 128, 32,
        bl1, br1, nullptr,
        d_xl1, d_xr1, d_res, 128, 128, 32,
        nullptr, nullptr);

    agg_conv1<<<nodeWarpBlocks, 256>>>(N, att1);

    bn_stats<128><<<256, 256>>>(d_agg1, bias1, N, d_sum1, d_sq1);
    bn_prep<<<1, 128>>>(d_sum1, d_sq1, N, 128, bn1_g, bn1_b, bias1, d_scale1, d_shift1);

    // conv2 transforms reading agg1 with on-the-fly BN + ELU
    transform_kernel<<<dim3(rowBlocks, 1), 256>>>(
        d_agg1, N, Wl2, Wr2, nullptr, 32, 32, 0,
        bl2, br2, nullptr,
        d_xl2, d_xr2, nullptr, 32, 32, 0,
        d_scale1, d_shift1);

    agg_conv2<<<nodeWarpBlocks, 256>>>(N, att2);

    bn_stats<32><<<256, 256>>>(d_agg2, bias2, N, d_sum2, d_sq2);
    bn_prep<<<1, 32>>>(d_sum2, d_sq2, N, 32, bn2_g, bn2_b, bias2, d_scale2, d_shift2);

    finalize_kernel<<<nodeWarpBlocks, 256>>>(linW, linb, out, N);
}